// round 15
// baseline (speedup 1.0000x reference)
#include <cuda_runtime.h>

// out[b, :] = table_bits[idx(b), :],  idx(b) = sum_k idx_bits[b,k] << (5-k)
// Table values are 0/1 pulses -> packed once into 64-bit masks (build kernel).
// Main kernel: each thread expands ONE mask byte -> 8 floats and writes them
// with a single 256-bit store (st.global.v8.f32, sm_100+). Halves STG count.

#define BATCH   262144
#define THREADS 256
#define ROWS_PER_WARP 16
#define GRID (BATCH / (ROWS_PER_WARP * (THREADS / 32)))   // 2048 blocks

// Mask for table row r: column c (0..63) lives at bit (63 - c).
__device__ unsigned long long g_masks[64];

__global__ void build_masks_kernel(const float* __restrict__ table)
{
    int w    = (blockIdx.x * blockDim.x + threadIdx.x) >> 5;   // 0..63 table row
    int lane = threadIdx.x & 31;
    float v0 = table[w * 64 + lane];        // cols 0..31
    float v1 = table[w * 64 + 32 + lane];   // cols 32..63
    unsigned hi = __brev(__ballot_sync(0xFFFFFFFFu, v0 > 0.5f)); // col c -> bit 31-c
    unsigned lo = __brev(__ballot_sync(0xFFFFFFFFu, v1 > 0.5f));
    if (lane == 0)
        g_masks[w] = ((unsigned long long)hi << 32) | (unsigned long long)lo;
}

__device__ __forceinline__ float byte_bit_to_1f(unsigned byte, int t)
{
    // byte bit (7-t) -> 0.0f / 1.0f  (1.0f = 0x3F800000)
    return __int_as_float(((int)(byte << (24 + t)) >> 31) & 0x3F800000);
}

__device__ __forceinline__ void stg256(float* p, const float* v)
{
    asm volatile("st.global.v8.f32 [%0], {%1,%2,%3,%4,%5,%6,%7,%8};"
                 :: "l"(p), "f"(v[0]), "f"(v[1]), "f"(v[2]), "f"(v[3]),
                    "f"(v[4]), "f"(v[5]), "f"(v[6]), "f"(v[7])
                 : "memory");
}

__global__ __launch_bounds__(THREADS)
void spike_lookup_kernel(const int* __restrict__ bits,    // BATCH*6
                         float*     __restrict__ out)     // BATCH*64
{
    const int lane  = threadIdx.x & 31;
    const int gwarp = blockIdx.x * (THREADS / 32) + (threadIdx.x >> 5);

    // 16 rows * 6 ints = 96 ints, fully coalesced.
    const int* __restrict__ p = bits + gwarp * 96;
    unsigned b0 = __ballot_sync(0xFFFFFFFFu, p[lane]      != 0); // int m -> bit m
    unsigned b1 = __ballot_sync(0xFFFFFFFFu, p[lane + 32] != 0);
    unsigned b2 = __ballot_sync(0xFFFFFFFFu, p[lane + 64] != 0);

    unsigned long long u01 = (unsigned long long)b0 | ((unsigned long long)b1 << 32);
    unsigned long long u12 = (unsigned long long)b1 | ((unsigned long long)b2 << 32);

    const int rlane = lane >> 3;          // 0..3: row within the 4-row group
    const int jj    = lane & 7;           // byte octet within the 64-float row
    const int sb    = 56 - 8 * jj;        // mask shift for this octet

    // Warp base: 16 rows * 64 floats = 1024 floats.
    float* __restrict__ wbase = out + (long long)gwarp * 1024;

    #pragma unroll
    for (int i = 0; i < 4; i++) {         // 4 groups of 4 rows
        int r  = 4 * i + rlane;           // local row 0..15
        int sh = 6 * r;
        unsigned vb = (r < 10) ? (unsigned)(u01 >> sh)
                               : (unsigned)(u12 >> (sh - 32));
        int idx = (int)(__brev(vb & 63u) >> 26);   // k=0 is MSB (weight 32)

        unsigned long long m = __ldg(&g_masks[idx]);   // L1-hot broadcast
        unsigned byte = (unsigned)(m >> sb) & 0xFFu;

        float v[8];
        #pragma unroll
        for (int t = 0; t < 8; t++)
            v[t] = byte_bit_to_1f(byte, t);

        // 32B contiguous per thread; warp covers 4 rows = 1KB contiguous.
        stg256(wbase + r * 64 + jj * 8, v);
    }
}

extern "C" void kernel_launch(void* const* d_in, const int* in_sizes, int n_in,
                              void* d_out, int out_size)
{
    const float* table = (const float*)d_in[0];
    const int*   bits  = (const int*)d_in[1];
    float*       out   = (float*)d_out;

    build_masks_kernel<<<2, 1024>>>(table);           // 64 warps, one per row
    spike_lookup_kernel<<<GRID, THREADS>>>(bits, out);
}